// round 14
// baseline (speedup 1.0000x reference)
#include <cuda_runtime.h>
#include <cuda_fp16.h>
#include <cstdint>

// ---------------- problem constants ----------------
#define BDIM   4096
#define IDIM   256
#define ODIM   256
#define KBASIS (IDIM * 64)           // 16384
#define KTOT   (KBASIS + 2 * IDIM)   // 16896
#define NTOT   (2 * ODIM)            // 512

// GEMM tiling: fine tiles to fill all 148 SMs via HW work distributor
#define MTILE  32
#define NTILE  64
#define KC     64                    // halves per stage-row = 128 B
#define STAGES 4
#define NST    (KTOT / KC)           // 264

// ---------------- scratch (device globals; no allocs allowed) ----------------
__device__ __align__(16) __half g_A[(size_t)BDIM * KTOT];    // 138 MB: [b][k] fp16
__device__ __align__(16) __half g_Wt[(size_t)NTOT * KTOT];   // 17.3 MB: [n][k] fp16 (K-major)
__device__ float g_bias[NTOT];

// ---------------- helpers ----------------
__device__ __forceinline__ uint32_t smem_u32(const void* p) {
    uint32_t a;
    asm("{ .reg .u64 t; cvta.to.shared.u64 t, %1; cvt.u32.u64 %0, t; }" : "=r"(a) : "l"(p));
    return a;
}

__device__ __forceinline__ void cp16s(uint32_t sm, const void* gm) {
    asm volatile("cp.async.cg.shared.global [%0], [%1], 16;\n" :: "r"(sm), "l"(gm) : "memory");
}

__device__ __forceinline__ void ldsm4(uint32_t* r, uint32_t addr) {
    asm volatile("ldmatrix.sync.aligned.m8n8.x4.shared.b16 {%0,%1,%2,%3}, [%4];"
                 : "=r"(r[0]), "=r"(r[1]), "=r"(r[2]), "=r"(r[3]) : "r"(addr));
}

__device__ __forceinline__ void mma_f16(float* d, const uint32_t* a, uint32_t b0, uint32_t b1) {
    asm volatile(
        "mma.sync.aligned.m16n8k16.row.col.f32.f16.f16.f32 "
        "{%0,%1,%2,%3},{%4,%5,%6,%7},{%8,%9},{%0,%1,%2,%3};"
        : "+f"(d[0]), "+f"(d[1]), "+f"(d[2]), "+f"(d[3])
        : "r"(a[0]), "r"(a[1]), "r"(a[2]), "r"(a[3]), "r"(b0), "r"(b1));
}

// ---------------- fused prep ----------------
// x-part: 4096 blocks, one b per block, one i per thread. No smem, no syncs.
#define XBLOCKS 4096
#define WT_BLOCKS 8192
#define WS_BLOCKS 1024

__global__ void prep_all(const float* __restrict__ xre, const float* __restrict__ xim,
                         const float* __restrict__ rw, const float* __restrict__ cw,
                         const float* __restrict__ swre, const float* __restrict__ swim,
                         const float* __restrict__ bre, const float* __restrict__ bim) {
    const int bid = blockIdx.x;
    const int t   = threadIdx.x;

    if (bid < XBLOCKS) {
        const int b = bid;
        const int i = t;
        const float xr = xre[b * IDIM + i];
        const float xi = xim[b * IDIM + i];

        float eu[8];
        __half2 ev[4];
#pragma unroll
        for (int u = 0; u < 8; u++) {
            float lu = -2.0f + (float)u * (4.0f / 7.0f);
            float dr = xr - lu;
            eu[u] = __expf(-dr * dr);
        }
#pragma unroll
        for (int vp = 0; vp < 4; vp++) {
            float l0 = -2.0f + (float)(2 * vp) * (4.0f / 7.0f);
            float l1 = l0 + (4.0f / 7.0f);
            float d0 = xi - l0, d1 = xi - l1;
            ev[vp] = __floats2half2_rn(__expf(-d0 * d0), __expf(-d1 * d1));
        }

        const size_t base = (size_t)b * KTOT + (size_t)i * 64;
#pragma unroll
        for (int u = 0; u < 8; u++) {
            __half2 b2 = __float2half2_rn(eu[u]);
            __half2 p0 = __hmul2(b2, ev[0]);
            __half2 p1 = __hmul2(b2, ev[1]);
            __half2 p2 = __hmul2(b2, ev[2]);
            __half2 p3 = __hmul2(b2, ev[3]);
            uint4 pack;
            pack.x = *(uint32_t*)&p0; pack.y = *(uint32_t*)&p1;
            pack.z = *(uint32_t*)&p2; pack.w = *(uint32_t*)&p3;
            *(uint4*)&g_A[base + u * 8] = pack;
        }

        g_A[(size_t)b * KTOT + KBASIS + i]       = __float2half_rn(xr / (1.0f + __expf(-xr)));
        g_A[(size_t)b * KTOT + KBASIS + 256 + i] = __float2half_rn(xi / (1.0f + __expf(-xi)));
    } else if (bid < XBLOCKS + WT_BLOCKS) {
        int idx = (bid - XBLOCKS) * 256 + t;
        int f4 = idx & 15;
        int i  = (idx >> 4) & 255;
        int n  = idx >> 12;
        int o = n >> 1, c = n & 1;
        const float* src = c ? cw : rw;
        float4 w = *(const float4*)&src[((size_t)(i * ODIM + o)) * 64 + f4 * 4];
        size_t dst = (size_t)n * KTOT + i * 64 + f4 * 4;
        *(__half2*)&g_Wt[dst]     = __floats2half2_rn(w.x, w.y);
        *(__half2*)&g_Wt[dst + 2] = __floats2half2_rn(w.z, w.w);
    } else if (bid < XBLOCKS + WT_BLOCKS + WS_BLOCKS) {
        int idx = (bid - XBLOCKS - WT_BLOCKS) * 256 + t;
        int j = idx & 511;
        int n = idx >> 9;
        int o = n >> 1, c = n & 1;
        float v;
        if (j < 256) { int i = j;       v = c ? swim[i * ODIM + o] : swre[i * ODIM + o]; }
        else         { int i = j - 256; v = c ? swre[i * ODIM + o] : -swim[i * ODIM + o]; }
        g_Wt[(size_t)n * KTOT + KBASIS + j] = __float2half_rn(v);
    } else {
        int n = bid - (XBLOCKS + WT_BLOCKS + WS_BLOCKS);
        int o = n >> 1;
        const float* src = (n & 1) ? bim : bre;
        float v = src[t * ODIM + o];
#pragma unroll
        for (int off = 16; off; off >>= 1) v += __shfl_down_sync(0xffffffffu, v, off);
        __shared__ float red[8];
        if ((t & 31) == 0) red[t >> 5] = v;
        __syncthreads();
        if (t == 0) {
            float s = 0.0f;
#pragma unroll
            for (int w = 0; w < 8; w++) s += red[w];
            g_bias[n] = s;
        }
    }
}

// ---------------- GEMM: fp16 mma, 32x64 tiles, 1024 CTAs, 2/SM ----------------
// warps: kg(2 k-groups) x wm(2 rows of 16) x wn(2 cols of 32); per-warp 16x32.
#define STAGE_A     (MTILE * 128)           // 4096 B
#define STAGE_B     (NTILE * 128)           // 8192 B
#define STAGE_BYTES (STAGE_A + STAGE_B)     // 12288 B
#define SMEM_BYTES  (STAGES * STAGE_BYTES)  // 49152 B

__device__ __forceinline__ void load_stage(uint32_t sbase, int m0, int n0, int kt, int buf, int tid) {
    uint32_t sa  = sbase + buf * STAGE_BYTES;
    uint32_t sbb = sa + STAGE_A;
    const __half* Ap = g_A  + (size_t)m0 * KTOT + (size_t)kt * KC;
    const __half* Bp = g_Wt + (size_t)n0 * KTOT + (size_t)kt * KC;
    {   // A: 256 chunks of 16B, one per thread
        int r = tid >> 3, c = tid & 7;
        cp16s(sa + (uint32_t)(r * 128 + ((c ^ (r & 7)) * 16)), Ap + (size_t)r * KTOT + c * 8);
    }
#pragma unroll
    for (int j = 0; j < 2; j++) {   // B: 512 chunks
        int id = tid + 256 * j;
        int r = id >> 3, c = id & 7;
        cp16s(sbb + (uint32_t)(r * 128 + ((c ^ (r & 7)) * 16)), Bp + (size_t)r * KTOT + c * 8);
    }
    asm volatile("cp.async.commit_group;" ::: "memory");
}

__global__ __launch_bounds__(256, 2) void gemm_kernel(float* __restrict__ out) {
    extern __shared__ char smem_raw[];
    const uint32_t sb = smem_u32(smem_raw);

    const int tid  = threadIdx.x;
    const int lane = tid & 31;
    const int warp = tid >> 5;
    const int kg   = warp >> 2;        // k-slice: k16 steps {0,1} vs {2,3}
    const int wm   = (warp >> 1) & 1;  // 2 rows of 16
    const int wn   = warp & 1;         // 2 cols of 32
    const int lr   = lane & 15;
    const int lh   = lane >> 4;
    // n fastest so the 8 CTAs sharing an A-slice are adjacent
    const int n0   = blockIdx.x * NTILE;
    const int m0   = blockIdx.y * MTILE;

    float acc[4][4];
#pragma unroll
    for (int b = 0; b < 4; b++)
#pragma unroll
        for (int c = 0; c < 4; c++) acc[b][c] = 0.0f;

    // prologue: stages 0..2
    load_stage(sb, m0, n0, 0, 0, tid);
    load_stage(sb, m0, n0, 1, 1, tid);
    load_stage(sb, m0, n0, 2, 2, tid);

    for (int kt = 0; kt < NST; kt++) {
        if (kt < NST - 2)       asm volatile("cp.async.wait_group 2;" ::: "memory");
        else if (kt == NST - 2) asm volatile("cp.async.wait_group 1;" ::: "memory");
        else                    asm volatile("cp.async.wait_group 0;" ::: "memory");
        __syncthreads();

        if (kt + 3 < NST) load_stage(sb, m0, n0, kt + 3, (kt + 3) & (STAGES - 1), tid);

        const int buf = kt & (STAGES - 1);
        const uint32_t sa  = sb + buf * STAGE_BYTES;
        const uint32_t sbb = sa + STAGE_A;

#pragma unroll
        for (int ksl = 0; ksl < 2; ksl++) {
            const int c = (kg * 2 + ksl) * 2 + lh;               // chunk 0..7
            const uint32_t cc = (uint32_t)((c ^ (lr & 7)) * 16);
            uint32_t afr[4];
            ldsm4(afr, sa + (uint32_t)(wm * 16 + lr) * 128 + cc);
            uint32_t bfr[2][4];
#pragma unroll
            for (int nb = 0; nb < 2; nb++)
                ldsm4(bfr[nb], sbb + (uint32_t)(wn * 32 + nb * 16 + lr) * 128 + cc);
#pragma unroll
            for (int nt = 0; nt < 4; nt++) {
                int nb = nt >> 1, hi = nt & 1;
                mma_f16(acc[nt], afr, bfr[nb][hi], bfr[nb][2 + hi]);
            }
        }
    }

    // ---------------- epilogue: merge k-slices via smem ----------------
    __syncthreads();   // all warps done reading stage buffers

    if (kg == 1) {
        float* dst = (float*)(smem_raw + (wm * 2 + wn) * 2048);
#pragma unroll
        for (int nt = 0; nt < 4; nt++) {
            float4 v = make_float4(acc[nt][0], acc[nt][1], acc[nt][2], acc[nt][3]);
            *(float4*)&dst[(nt * 32 + lane) * 4] = v;
        }
    }
    __syncthreads();

    if (kg == 0) {
        const float* prt = (const float*)(smem_raw + (wm * 2 + wn) * 2048);
        const int gid = lane >> 2;
        const int tg  = lane & 3;
#pragma unroll
        for (int nt = 0; nt < 4; nt++) {
            float4 p = *(const float4*)&prt[(nt * 32 + lane) * 4];
            int row = m0 + wm * 16 + gid;
            int col = n0 + wn * 32 + nt * 8 + tg * 2;
            float2 bb = *(const float2*)&g_bias[col];
            float2 v0 = make_float2(acc[nt][0] + p.x + bb.x, acc[nt][1] + p.y + bb.y);
            float2 v1 = make_float2(acc[nt][2] + p.z + bb.x, acc[nt][3] + p.w + bb.y);
            *(float2*)&out[(size_t)row * NTOT + col]       = v0;
            *(float2*)&out[(size_t)(row + 8) * NTOT + col] = v1;
        }
    }
}

// ---------------- launch ----------------
extern "C" void kernel_launch(void* const* d_in, const int* in_sizes, int n_in,
                              void* d_out, int out_size) {
    const float* xre  = (const float*)d_in[0];
    const float* xim  = (const float*)d_in[1];
    const float* rw   = (const float*)d_in[2];
    const float* cw   = (const float*)d_in[3];
    const float* swre = (const float*)d_in[4];
    const float* swim = (const float*)d_in[5];
    const float* bre  = (const float*)d_in[6];
    const float* bim  = (const float*)d_in[7];
    float* out = (float*)d_out;

    static bool attr_set = false;
    if (!attr_set) {
        cudaFuncSetAttribute(gemm_kernel, cudaFuncAttributeMaxDynamicSharedMemorySize, SMEM_BYTES);
        attr_set = true;
    }

    prep_all<<<XBLOCKS + WT_BLOCKS + WS_BLOCKS + NTOT, 256>>>(
        xre, xim, rw, cw, swre, swim, bre, bim);
    gemm_kernel<<<dim3(NTOT / NTILE, BDIM / MTILE), 256, SMEM_BYTES>>>(out);
}

// round 15
// speedup vs baseline: 1.9833x; 1.9833x over previous
#include <cuda_runtime.h>
#include <cuda_fp16.h>
#include <cstdint>

// ---------------- problem constants ----------------
#define BDIM   4096
#define IDIM   256
#define ODIM   256
#define KBASIS (IDIM * 64)           // 16384
#define KTOT   (KBASIS + 2 * IDIM)   // 16896
#define NTOT   (2 * ODIM)            // 512

// GEMM tiling
#define MTILE  128
#define NTILE  128
#define KC     128                   // halves per stage-row = 256 B
#define STAGES 3
#define NST    (KTOT / KC)           // 132 (stages 0..127 basis, 128..131 silu)
#define NBASIS_ST 128

// ---------------- scratch (device globals; no allocs allowed) ----------------
__device__ __align__(16) __half g_EU[(size_t)BDIM * IDIM * 8];   // 16 MB [b][i][u]
__device__ __align__(16) __half g_EV[(size_t)BDIM * IDIM * 8];   // 16 MB [b][i][v]
__device__ __align__(16) __half g_Asilu[(size_t)BDIM * 512];     // 4 MB  [b][j]
__device__ __align__(16) __half g_Wt[(size_t)NTOT * KTOT];       // 17.3 MB [n][k] K-major
__device__ float g_bias[NTOT];

// ---------------- helpers ----------------
__device__ __forceinline__ uint32_t smem_u32(const void* p) {
    uint32_t a;
    asm("{ .reg .u64 t; cvta.to.shared.u64 t, %1; cvt.u32.u64 %0, t; }" : "=r"(a) : "l"(p));
    return a;
}

__device__ __forceinline__ void cp16s(uint32_t sm, const void* gm) {
    asm volatile("cp.async.cg.shared.global [%0], [%1], 16;\n" :: "r"(sm), "l"(gm) : "memory");
}

__device__ __forceinline__ void sts128(uint32_t sm, uint32_t a, uint32_t b, uint32_t c, uint32_t d) {
    asm volatile("st.shared.v4.b32 [%0], {%1,%2,%3,%4};" :: "r"(sm), "r"(a), "r"(b), "r"(c), "r"(d) : "memory");
}

__device__ __forceinline__ void ldsm4(uint32_t* r, uint32_t addr) {
    asm volatile("ldmatrix.sync.aligned.m8n8.x4.shared.b16 {%0,%1,%2,%3}, [%4];"
                 : "=r"(r[0]), "=r"(r[1]), "=r"(r[2]), "=r"(r[3]) : "r"(addr));
}

__device__ __forceinline__ void mma_f16(float* d, const uint32_t* a, uint32_t b0, uint32_t b1) {
    asm volatile(
        "mma.sync.aligned.m16n8k16.row.col.f32.f16.f16.f32 "
        "{%0,%1,%2,%3},{%4,%5,%6,%7},{%8,%9},{%0,%1,%2,%3};"
        : "+f"(d[0]), "+f"(d[1]), "+f"(d[2]), "+f"(d[3])
        : "r"(a[0]), "r"(a[1]), "r"(a[2]), "r"(a[3]), "r"(b0), "r"(b1));
}

// ---------------- prep: EU/EV tables, silu rows, weights, bias ----------------
#define XBLOCKS 4096
#define WT_BLOCKS 8192
#define WS_BLOCKS 1024

__global__ void prep_all(const float* __restrict__ xre, const float* __restrict__ xim,
                         const float* __restrict__ rw, const float* __restrict__ cw,
                         const float* __restrict__ swre, const float* __restrict__ swim,
                         const float* __restrict__ bre, const float* __restrict__ bim) {
    const int bid = blockIdx.x;
    const int t   = threadIdx.x;

    if (bid < XBLOCKS) {
        const int b = bid;
        const int i = t;
        const float xr = xre[b * IDIM + i];
        const float xi = xim[b * IDIM + i];

        __half eu[8], ev[8];
#pragma unroll
        for (int u = 0; u < 8; u++) {
            float lu = -2.0f + (float)u * (4.0f / 7.0f);
            float dr = xr - lu;
            float di = xi - lu;
            eu[u] = __float2half_rn(__expf(-dr * dr));
            ev[u] = __float2half_rn(__expf(-di * di));
        }
        const size_t off = ((size_t)b * IDIM + i) * 8;
        *(uint4*)&g_EU[off] = *(const uint4*)eu;
        *(uint4*)&g_EV[off] = *(const uint4*)ev;

        g_Asilu[(size_t)b * 512 + i]       = __float2half_rn(xr / (1.0f + __expf(-xr)));
        g_Asilu[(size_t)b * 512 + 256 + i] = __float2half_rn(xi / (1.0f + __expf(-xi)));
    } else if (bid < XBLOCKS + WT_BLOCKS) {
        int idx = (bid - XBLOCKS) * 256 + t;
        int f4 = idx & 15;
        int i  = (idx >> 4) & 255;
        int n  = idx >> 12;
        int o = n >> 1, c = n & 1;
        const float* src = c ? cw : rw;
        float4 w = *(const float4*)&src[((size_t)(i * ODIM + o)) * 64 + f4 * 4];
        size_t dst = (size_t)n * KTOT + i * 64 + f4 * 4;
        *(__half2*)&g_Wt[dst]     = __floats2half2_rn(w.x, w.y);
        *(__half2*)&g_Wt[dst + 2] = __floats2half2_rn(w.z, w.w);
    } else if (bid < XBLOCKS + WT_BLOCKS + WS_BLOCKS) {
        int idx = (bid - XBLOCKS - WT_BLOCKS) * 256 + t;
        int j = idx & 511;
        int n = idx >> 9;
        int o = n >> 1, c = n & 1;
        float v;
        if (j < 256) { int i = j;       v = c ? swim[i * ODIM + o] : swre[i * ODIM + o]; }
        else         { int i = j - 256; v = c ? swre[i * ODIM + o] : -swim[i * ODIM + o]; }
        g_Wt[(size_t)n * KTOT + KBASIS + j] = __float2half_rn(v);
    } else {
        int n = bid - (XBLOCKS + WT_BLOCKS + WS_BLOCKS);
        int o = n >> 1;
        const float* src = (n & 1) ? bim : bre;
        float v = src[t * ODIM + o];
#pragma unroll
        for (int off = 16; off; off >>= 1) v += __shfl_down_sync(0xffffffffu, v, off);
        __shared__ float red[8];
        if ((t & 31) == 0) red[t >> 5] = v;
        __syncthreads();
        if (t == 0) {
            float s = 0.0f;
#pragma unroll
            for (int w = 0; w < 8; w++) s += red[w];
            g_bias[n] = s;
        }
    }
}

// ---------------- GEMM: warp-specialized. 384 threads: 8 consumer + 4 producer warps ----
// A-stages expanded in-smem by producer warps from EU/EV (basis) or cp.async (silu).
// B always cp.async by producers. Consumers: pure ldsm + mma (R8 mainloop).
#define STAGE_A     (MTILE * 256)           // 32768 B
#define STAGE_BYTES (2 * STAGE_A)           // 65536 B
#define SMEM_BYTES  (STAGES * STAGE_BYTES)  // 196608 B

// producer: expand/copy A-stage kt into buffer, then cp.async B-stage kt, commit.
__device__ __forceinline__ void produce_stage(uint32_t sbase, int m0, int n0, int kt, int buf, int pt) {
    // pt = producer thread id 0..127; one A-row each.
    uint32_t sa  = sbase + buf * STAGE_BYTES;
    uint32_t sbb = sa + STAGE_A;
    const int r = pt;
    const uint32_t rowbase = sa + (uint32_t)r * 256;

    if (kt < NBASIS_ST) {
        // rank-1 expansion: k = kt*128 + c*8 + e ; i = 2kt + (c>>3), u = c&7, v = e
        const size_t toff = ((size_t)(m0 + r) * IDIM + kt * 2) * 8;
        __half  eu[16];
        __half2 ev[8];
        *(uint4*)eu       = *(const uint4*)&g_EU[toff];
        *(uint4*)(eu + 8) = *(const uint4*)&g_EU[toff + 8];
        *(uint4*)ev       = *(const uint4*)&g_EV[toff];
        *(uint4*)(ev + 4) = *(const uint4*)&g_EV[toff + 8];
#pragma unroll
        for (int c = 0; c < 16; c++) {
            const int ii = c >> 3;
            const __half2 b2 = __half2half2(eu[c]);      // eu[ii*8 + (c&7)] == eu[c]
            __half2 p0 = __hmul2(b2, ev[ii * 4 + 0]);
            __half2 p1 = __hmul2(b2, ev[ii * 4 + 1]);
            __half2 p2 = __hmul2(b2, ev[ii * 4 + 2]);
            __half2 p3 = __hmul2(b2, ev[ii * 4 + 3]);
            uint32_t off = rowbase + (uint32_t)((c >> 3) * 128 + (((c & 7) ^ (r & 7)) * 16));
            sts128(off, *(uint32_t*)&p0, *(uint32_t*)&p1, *(uint32_t*)&p2, *(uint32_t*)&p3);
        }
    } else {
        // silu rows via cp.async (joins this stage's commit group)
        const __half* Ap = g_Asilu + (size_t)(m0 + r) * 512 + (size_t)(kt - NBASIS_ST) * KC;
#pragma unroll
        for (int c = 0; c < 16; c++) {
            uint32_t off = rowbase + (uint32_t)((c >> 3) * 128 + (((c & 7) ^ (r & 7)) * 16));
            cp16s(off, Ap + c * 8);
        }
    }

    // B: 128 rows x 256B = 2048 chunks / 128 producers = 16 each
    const __half* Bp = g_Wt + (size_t)n0 * KTOT + (size_t)kt * KC;
#pragma unroll
    for (int j = 0; j < 16; j++) {
        int id = pt + 128 * j;
        int br = id >> 4, bc = id & 15;
        uint32_t off = (uint32_t)(br * 256 + (bc >> 3) * 128 + (((bc & 7) ^ (br & 7)) * 16));
        cp16s(sbb + off, Bp + (size_t)br * KTOT + bc * 8);
    }
    asm volatile("cp.async.commit_group;" ::: "memory");
}

__global__ __launch_bounds__(384, 1) void gemm_kernel(float* __restrict__ out) {
    extern __shared__ char smem_raw[];
    const uint32_t sb = smem_u32(smem_raw);

    const int tid  = threadIdx.x;
    const int lane = tid & 31;
    const int warp = tid >> 5;
    const bool is_producer = (warp >= 8);
    const int pt   = tid - 256;        // producer thread id (valid when is_producer)
    // n fastest so the 4 CTAs sharing EU/EV slices are adjacent
    const int n0   = blockIdx.x * NTILE;
    const int m0   = blockIdx.y * MTILE;

    // consumer decomposition: 2 warp-rows of 64 x 4 warp-cols of 32
    const int wm   = warp >> 2;        // 0..1 (consumers only)
    const int wn   = warp & 3;         // 0..3
    const int lr   = lane & 15;
    const int lh   = lane >> 4;

    float acc[4][4][4];
#pragma unroll
    for (int a = 0; a < 4; a++)
#pragma unroll
        for (int b = 0; b < 4; b++)
#pragma unroll
            for (int c = 0; c < 4; c++) acc[a][b][c] = 0.0f;

    // prologue: producers fill stages 0,1
    if (is_producer) {
        produce_stage(sb, m0, n0, 0, 0, pt);
        produce_stage(sb, m0, n0, 1, 1, pt);
        asm volatile("cp.async.wait_group 1;" ::: "memory");   // stage 0 B complete
    }
    __syncthreads();

    uint32_t afr[2][4][4];
    uint32_t bfr[2][2][4];

    for (int kt = 0; kt < NST; kt++) {
        const int buf = kt % STAGES;

        if (is_producer) {
            if (kt + 2 < NST) {
                produce_stage(sb, m0, n0, kt + 2, (kt + 2) % STAGES, pt);
                asm volatile("cp.async.wait_group 1;" ::: "memory");  // stage kt+1 complete
            } else {
                asm volatile("cp.async.wait_group 0;" ::: "memory");
            }
        } else {
            const uint32_t sa  = sb + buf * STAGE_BYTES;
            const uint32_t sbb = sa + STAGE_A;

            // fragment ks=0
            {
                const int c = lh;
                const uint32_t cc = (uint32_t)((c >> 3) * 128 + (((c & 7) ^ (lr & 7)) * 16));
#pragma unroll
                for (int mt = 0; mt < 4; mt++)
                    ldsm4(afr[0][mt], sa + (uint32_t)(wm * 64 + mt * 16 + lr) * 256 + cc);
#pragma unroll
                for (int nb = 0; nb < 2; nb++)
                    ldsm4(bfr[0][nb], sbb + (uint32_t)(wn * 32 + nb * 16 + lr) * 256 + cc);
            }
#pragma unroll
            for (int ks = 0; ks < 8; ks++) {
                const int cur = ks & 1;
                if (ks < 7) {
                    const int nxt = cur ^ 1;
                    const int c = (ks + 1) * 2 + lh;
                    const uint32_t cc = (uint32_t)((c >> 3) * 128 + (((c & 7) ^ (lr & 7)) * 16));
#pragma unroll
                    for (int mt = 0; mt < 4; mt++)
                        ldsm4(afr[nxt][mt], sa + (uint32_t)(wm * 64 + mt * 16 + lr) * 256 + cc);
#pragma unroll
                    for (int nb = 0; nb < 2; nb++)
                        ldsm4(bfr[nxt][nb], sbb + (uint32_t)(wn * 32 + nb * 16 + lr) * 256 + cc);
                }
#pragma unroll
                for (int mt = 0; mt < 4; mt++)
#pragma unroll
                    for (int nt = 0; nt < 4; nt++) {
                        int nb = nt >> 1, hi = nt & 1;
                        mma_f16(acc[mt][nt], afr[cur][mt], bfr[cur][nb][hi], bfr[cur][nb][2 + hi]);
                    }
            }
        }
        __syncthreads();
    }

    // epilogue: consumers write out (no k-split merge needed)
    if (!is_producer) {
        const int gid = lane >> 2;
        const int tg  = lane & 3;
#pragma unroll
        for (int mt = 0; mt < 4; mt++) {
#pragma unroll
            for (int nt = 0; nt < 4; nt++) {
                int row = m0 + wm * 64 + mt * 16 + gid;
                int col = n0 + wn * 32 + nt * 8 + tg * 2;
                float2 bb = *(const float2*)&g_bias[col];
                float2 v0 = make_float2(acc[mt][nt][0] + bb.x, acc[mt][nt][1] + bb.y);
                float2 v1 = make_float2(acc[mt][nt][2] + bb.x, acc[mt][nt][3] + bb.y);
                *(float2*)&out[(size_t)row * NTOT + col]       = v0;
                *(float2*)&out[(size_t)(row + 8) * NTOT + col] = v1;
            }
        }
    }
}

// ---------------- launch ----------------
extern "C" void kernel_launch(void* const* d_in, const int* in_sizes, int n_in,
                              void* d_out, int out_size) {
    const float* xre  = (const float*)d_in[0];
    const float* xim  = (const float*)d_in[1];
    const float* rw   = (const float*)d_in[2];
    const float* cw   = (const float*)d_in[3];
    const float* swre = (const float*)d_in[4];
    const float* swim = (const float*)d_in[5];
    const float* bre  = (const float*)d_in[6];
    const float* bim  = (const float*)d_in[7];
    float* out = (float*)d_out;

    static bool attr_set = false;
    if (!attr_set) {
        cudaFuncSetAttribute(gemm_kernel, cudaFuncAttributeMaxDynamicSharedMemorySize, SMEM_BYTES);
        attr_set = true;
    }

    prep_all<<<XBLOCKS + WT_BLOCKS + WS_BLOCKS + NTOT, 256>>>(
        xre, xim, rw, cw, swre, swim, bre, bim);
    gemm_kernel<<<dim3(NTOT / NTILE, BDIM / MTILE), 384, SMEM_BYTES>>>(out);
}